// round 5
// baseline (speedup 1.0000x reference)
#include <cuda_runtime.h>
#include <cuda_bf16.h>
#include <math_constants.h>

#define B        256
#define N_IN     4096
#define N_MID    4096
#define N_OUT    1024

// Routing tables + completion counter (device globals — no allocation allowed)
__device__ int g_dest1[N_IN];
__device__ int g_dest2[N_MID];
__device__ int g_dest3[N_MID];          // W3 has 4096 rows
__device__ int g_route[N_IN];           // composed dest3[dest2[dest1[s]]]
__device__ unsigned int g_done;         // zero-initialized; reset by last block

__device__ __forceinline__ void amax_combine(float& v, int& i, float ov, int oi) {
    if (ov > v || (ov == v && oi < i)) { v = ov; i = oi; }
}

__device__ __forceinline__ void proc4(const float4& v, int base, float& best, int& bidx) {
    if (v.x > best) { best = v.x; bidx = base;     }
    if (v.y > best) { best = v.y; bidx = base + 1; }
    if (v.z > best) { best = v.z; bidx = base + 2; }
    if (v.w > best) { best = v.w; bidx = base + 3; }
}

// ---------------------------------------------------------------------------
// One fused argmax launch for all three weight matrices.
// Blocks [0,4096)     -> W1 rows (4096 cols)
// Blocks [4096,8192)  -> W2 rows (4096 cols)
// Blocks [8192,12288) -> W3 rows (1024 cols)
// The LAST block to finish additionally composes the route table, so the
// scatter kernel never chases the dest chain.
// ---------------------------------------------------------------------------
__global__ void __launch_bounds__(256) argmax_all_kernel(
    const float* __restrict__ W1, const float* __restrict__ W2,
    const float* __restrict__ W3)
{
    const int bid = blockIdx.x;
    const int tid = threadIdx.x;

    const float* W;
    int* dest;
    int row;
    bool wide;           // 4096 cols vs 1024 cols
    if (bid < N_IN) {
        W = W1; dest = g_dest1; row = bid;          wide = true;
    } else if (bid < 2 * N_IN) {
        W = W2; dest = g_dest2; row = bid - N_IN;   wide = true;
    } else {
        W = W3; dest = g_dest3; row = bid - 2*N_IN; wide = false;
    }

    float best = -CUDART_INF_F;
    int   bidx = 0;

    if (wide) {
        const float4* __restrict__ r4 =
            reinterpret_cast<const float4*>(W + (size_t)row * N_MID);
        // Batch all 4 loads first (front-batched MLP), then compare in
        // increasing index order (strict '>' keeps earliest index).
        float4 a = r4[tid];
        float4 b = r4[tid + 256];
        float4 c = r4[tid + 512];
        float4 d = r4[tid + 768];
        proc4(a, (tid      ) * 4, best, bidx);
        proc4(b, (tid + 256) * 4, best, bidx);
        proc4(c, (tid + 512) * 4, best, bidx);
        proc4(d, (tid + 768) * 4, best, bidx);
    } else {
        const float4* __restrict__ r4 =
            reinterpret_cast<const float4*>(W + (size_t)row * N_OUT);
        float4 a = r4[tid];
        proc4(a, tid * 4, best, bidx);
    }

    // Warp reduction (tie -> smaller index)
    #pragma unroll
    for (int off = 16; off > 0; off >>= 1) {
        float ov = __shfl_down_sync(0xFFFFFFFFu, best, off);
        int   oi = __shfl_down_sync(0xFFFFFFFFu, bidx, off);
        amax_combine(best, bidx, ov, oi);
    }

    // Cross-warp reduction (8 warps)
    __shared__ float s_val[8];
    __shared__ int   s_idx[8];
    const int lane = tid & 31;
    const int wid  = tid >> 5;
    if (lane == 0) { s_val[wid] = best; s_idx[wid] = bidx; }
    __syncthreads();

    __shared__ bool s_last;
    if (tid == 0) {
        float v = s_val[0]; int i = s_idx[0];
        #pragma unroll
        for (int w = 1; w < 8; w++) amax_combine(v, i, s_val[w], s_idx[w]);
        dest[row] = i;
        __threadfence();                       // publish dest before counting
        unsigned prev = atomicAdd(&g_done, 1u);
        s_last = (prev == 3u * N_IN - 1u);
    }
    __syncthreads();

    // Last block composes route[s] = dest3[dest2[dest1[s]]].
    // All tables are L2-hot; 16 independent chains/thread hide the latency.
    if (s_last) {
        __threadfence();                       // acquire all dest writes
        #pragma unroll
        for (int it = 0; it < N_IN / 256; ++it) {
            int s = tid + it * 256;
            g_route[s] = g_dest3[g_dest2[g_dest1[s]]];
        }
        if (tid == 0) g_done = 0;              // reset for next graph replay
    }
}

// ---------------------------------------------------------------------------
// Scatter: one block (512 threads) per batch. Chain-free: coalesced int4
// loads of x and the precomputed route, shared-memory atomics, float store.
// ---------------------------------------------------------------------------
__global__ void __launch_bounds__(512) scatter_kernel(
    const int* __restrict__ x, float* __restrict__ out)
{
    __shared__ int acc[N_OUT];
    const int b   = blockIdx.x;
    const int tid = threadIdx.x;

    #pragma unroll
    for (int i = tid; i < N_OUT; i += 512) acc[i] = 0;
    __syncthreads();

    const int4* __restrict__ xb4 =
        reinterpret_cast<const int4*>(x + (size_t)b * N_IN);
    const int4* __restrict__ r4 = reinterpret_cast<const int4*>(g_route);

    #pragma unroll
    for (int it = 0; it < N_IN / 4 / 512; ++it) {
        const int i = tid + it * 512;
        int4 v = xb4[i];                 // DRAM stream
        int4 r = r4[i];                  // L2-hot, coalesced
        atomicAdd(&acc[r.x], v.x);
        atomicAdd(&acc[r.y], v.y);
        atomicAdd(&acc[r.z], v.z);
        atomicAdd(&acc[r.w], v.w);
    }
    __syncthreads();

    float* __restrict__ ob = out + (size_t)b * N_OUT;
    #pragma unroll
    for (int i = tid; i < N_OUT; i += 512)
        ob[i] = (float)acc[i];
}

// ---------------------------------------------------------------------------
extern "C" void kernel_launch(void* const* d_in, const int* in_sizes, int n_in,
                              void* d_out, int out_size)
{
    const int*   x  = (const int*)d_in[0];
    const float* W1 = (const float*)d_in[1];
    const float* W2 = (const float*)d_in[2];
    const float* W3 = (const float*)d_in[3];
    float* out = (float*)d_out;

    argmax_all_kernel<<<3 * N_IN, 256>>>(W1, W2, W3);
    scatter_kernel<<<B, 512>>>(x, out);
}

// round 7
// speedup vs baseline: 1.3961x; 1.3961x over previous
#include <cuda_runtime.h>
#include <cuda_bf16.h>
#include <math_constants.h>

#define B        256
#define N_IN     4096
#define N_MID    4096
#define N_OUT    1024

// Scratch (device globals — no allocation allowed)
__device__ int g_dest1[N_IN];
__device__ int g_dest2[N_MID];
__device__ int g_dest3[N_MID];          // W3 has 4096 rows
__device__ int g_off[N_OUT + 1];        // CSR offsets (exclusive)
__device__ int g_srclist[N_IN];         // CSR source indices grouped by dest

__device__ __forceinline__ void amax_combine(float& v, int& i, float ov, int oi) {
    if (ov > v || (ov == v && oi < i)) { v = ov; i = oi; }
}

__device__ __forceinline__ void proc4(const float4& v, int base, float& best, int& bidx) {
    if (v.x > best) { best = v.x; bidx = base;     }
    if (v.y > best) { best = v.y; bidx = base + 1; }
    if (v.z > best) { best = v.z; bidx = base + 2; }
    if (v.w > best) { best = v.w; bidx = base + 3; }
}

// ---------------------------------------------------------------------------
// Fused argmax over all three weight matrices (R4 winner, no tail, no fences).
// ---------------------------------------------------------------------------
__global__ void __launch_bounds__(256) argmax_all_kernel(
    const float* __restrict__ W1, const float* __restrict__ W2,
    const float* __restrict__ W3)
{
    const int bid = blockIdx.x;
    const int tid = threadIdx.x;

    const float* W;
    int* dest;
    int row;
    bool wide;
    if (bid < N_IN) {
        W = W1; dest = g_dest1; row = bid;          wide = true;
    } else if (bid < 2 * N_IN) {
        W = W2; dest = g_dest2; row = bid - N_IN;   wide = true;
    } else {
        W = W3; dest = g_dest3; row = bid - 2*N_IN; wide = false;
    }

    float best = -CUDART_INF_F;
    int   bidx = 0;

    if (wide) {
        const float4* __restrict__ r4 =
            reinterpret_cast<const float4*>(W + (size_t)row * N_MID);
        float4 a = r4[tid];
        float4 b = r4[tid + 256];
        float4 c = r4[tid + 512];
        float4 d = r4[tid + 768];
        proc4(a, (tid      ) * 4, best, bidx);
        proc4(b, (tid + 256) * 4, best, bidx);
        proc4(c, (tid + 512) * 4, best, bidx);
        proc4(d, (tid + 768) * 4, best, bidx);
    } else {
        const float4* __restrict__ r4 =
            reinterpret_cast<const float4*>(W + (size_t)row * N_OUT);
        float4 a = r4[tid];
        proc4(a, tid * 4, best, bidx);
    }

    #pragma unroll
    for (int off = 16; off > 0; off >>= 1) {
        float ov = __shfl_down_sync(0xFFFFFFFFu, best, off);
        int   oi = __shfl_down_sync(0xFFFFFFFFu, bidx, off);
        amax_combine(best, bidx, ov, oi);
    }

    __shared__ float s_val[8];
    __shared__ int   s_idx[8];
    const int lane = tid & 31;
    const int wid  = tid >> 5;
    if (lane == 0) { s_val[wid] = best; s_idx[wid] = bidx; }
    __syncthreads();
    if (tid == 0) {
        float v = s_val[0]; int i = s_idx[0];
        #pragma unroll
        for (int w = 1; w < 8; w++) amax_combine(v, i, s_val[w], s_idx[w]);
        dest[row] = i;
    }
}

// ---------------------------------------------------------------------------
// Single-block build kernel: compose route, histogram per destination,
// prefix-sum, CSR fill. 1024 threads, runs once between argmax and scatter.
// Fill order within a segment is atomic-order nondeterministic, but only the
// SET of sources per segment matters (int adds commute) -> output values are
// deterministic.
// ---------------------------------------------------------------------------
__global__ void __launch_bounds__(1024) build_kernel()
{
    const int tid = threadIdx.x;
    __shared__ int s_cnt[N_OUT];
    __shared__ int s_scanA[N_OUT];
    __shared__ int s_cur[N_OUT];

    if (tid < N_OUT) s_cnt[tid] = 0;
    __syncthreads();

    // Compose route (4 chains per thread, independent -> latency overlapped)
    int r[N_IN / 1024];
    #pragma unroll
    for (int it = 0; it < N_IN / 1024; ++it) {
        int s = tid + it * 1024;
        r[it] = g_dest3[g_dest2[g_dest1[s]]];
    }
    #pragma unroll
    for (int it = 0; it < N_IN / 1024; ++it)
        atomicAdd(&s_cnt[r[it]], 1);
    __syncthreads();

    // Hillis-Steele inclusive scan over 1024 bins (first 1024 threads)
    if (tid < N_OUT) s_scanA[tid] = s_cnt[tid];
    __syncthreads();
    #pragma unroll
    for (int d = 1; d < N_OUT; d <<= 1) {
        int v = 0;
        if (tid < N_OUT) {
            v = s_scanA[tid];
            if (tid >= d) v += s_scanA[tid - d];
        }
        __syncthreads();
        if (tid < N_OUT) s_scanA[tid] = v;
        __syncthreads();
    }

    if (tid < N_OUT) {
        int excl = s_scanA[tid] - s_cnt[tid];
        g_off[tid] = excl;
        s_cur[tid] = excl;
    }
    if (tid == 0) g_off[N_OUT] = N_IN;
    __syncthreads();

    // Fill CSR
    #pragma unroll
    for (int it = 0; it < N_IN / 1024; ++it) {
        int s = tid + it * 1024;
        int pos = atomicAdd(&s_cur[r[it]], 1);
        g_srclist[pos] = s;
    }
}

// ---------------------------------------------------------------------------
// Atomic-free scatter: grid = (batch, half). Each block stages its x row
// (16KB) and the shared src_list (16KB) in smem, then each thread computes
// output bins as segmented sums. All gathers hit shared memory.
// ---------------------------------------------------------------------------
__global__ void __launch_bounds__(256) scatter_kernel(
    const int* __restrict__ x, float* __restrict__ out)
{
    __shared__ int sx[N_IN];
    __shared__ int slist[N_IN];

    const int b    = blockIdx.x >> 1;
    const int half = blockIdx.x & 1;
    const int tid  = threadIdx.x;

    // Stage x row + src_list, coalesced int4
    const int4* __restrict__ xb4 =
        reinterpret_cast<const int4*>(x + (size_t)b * N_IN);
    const int4* __restrict__ sl4 = reinterpret_cast<const int4*>(g_srclist);
    int4* __restrict__ sx4 = reinterpret_cast<int4*>(sx);
    int4* __restrict__ sls4 = reinterpret_cast<int4*>(slist);
    #pragma unroll
    for (int it = 0; it < N_IN / 4 / 256; ++it) {
        sx4 [tid + it * 256] = xb4[tid + it * 256];
        sls4[tid + it * 256] = sl4[tid + it * 256];
    }
    __syncthreads();

    float* __restrict__ ob = out + (size_t)b * N_OUT;
    #pragma unroll
    for (int o = 0; o < 2; ++o) {
        int f = half * (N_OUT / 2) + o * 256 + tid;
        int beg = g_off[f];
        int end = g_off[f + 1];
        int sum = 0;
        for (int i = beg; i < end; ++i)
            sum += sx[slist[i]];
        ob[f] = (float)sum;
    }
}

// ---------------------------------------------------------------------------
extern "C" void kernel_launch(void* const* d_in, const int* in_sizes, int n_in,
                              void* d_out, int out_size)
{
    const int*   x  = (const int*)d_in[0];
    const float* W1 = (const float*)d_in[1];
    const float* W2 = (const float*)d_in[2];
    const float* W3 = (const float*)d_in[3];
    float* out = (float*)d_out;

    argmax_all_kernel<<<3 * N_IN, 256>>>(W1, W2, W3);
    build_kernel<<<1, 1024>>>();
    scatter_kernel<<<2 * B, 256>>>(x, out);
}

// round 8
// speedup vs baseline: 1.7385x; 1.2452x over previous
#include <cuda_runtime.h>
#include <cuda_bf16.h>
#include <math_constants.h>

#define B        256
#define N_IN     4096
#define N_MID    4096
#define N_OUT    1024

// Scratch (device globals — no allocation allowed)
__device__ __align__(16) int g_dest1[N_IN];
__device__ __align__(16) int g_dest2[N_MID];
__device__ __align__(16) int g_dest3[N_MID];   // W3 has 4096 rows
__device__ __align__(16) int g_route[N_IN];    // dest3[dest2[dest1[s]]]

// ---------------------------------------------------------------------------
// Fused argmax over all three weight matrices.
// Blocks [0,4096)->W1, [4096,8192)->W2, [8192,12288)->W3.
// Strategy: front-batched float4 loads, shallow fmax tree to block max,
// then index recovery via min-reduce over positions equal to the max
// (ties -> smallest index, matching jnp.argmax).
// ---------------------------------------------------------------------------
__global__ void __launch_bounds__(256) argmax_all_kernel(
    const float* __restrict__ W1, const float* __restrict__ W2,
    const float* __restrict__ W3)
{
    const int bid = blockIdx.x;
    const int tid = threadIdx.x;
    const int lane = tid & 31;
    const int wid  = tid >> 5;

    const float* W;
    int* dest;
    int row;
    bool wide;
    if (bid < N_IN) {
        W = W1; dest = g_dest1; row = bid;          wide = true;
    } else if (bid < 2 * N_IN) {
        W = W2; dest = g_dest2; row = bid - N_IN;   wide = true;
    } else {
        W = W3; dest = g_dest3; row = bid - 2*N_IN; wide = false;
    }

    float4 a, b, c, d;
    float m;
    if (wide) {
        const float4* __restrict__ r4 =
            reinterpret_cast<const float4*>(W + (size_t)row * N_MID);
        a = r4[tid];
        b = r4[tid + 256];
        c = r4[tid + 512];
        d = r4[tid + 768];
        float m0 = fmaxf(fmaxf(a.x, a.y), fmaxf(a.z, a.w));
        float m1 = fmaxf(fmaxf(b.x, b.y), fmaxf(b.z, b.w));
        float m2 = fmaxf(fmaxf(c.x, c.y), fmaxf(c.z, c.w));
        float m3 = fmaxf(fmaxf(d.x, d.y), fmaxf(d.z, d.w));
        m = fmaxf(fmaxf(m0, m1), fmaxf(m2, m3));
    } else {
        const float4* __restrict__ r4 =
            reinterpret_cast<const float4*>(W + (size_t)row * N_OUT);
        a = r4[tid];
        m = fmaxf(fmaxf(a.x, a.y), fmaxf(a.z, a.w));
    }

    // Warp max
    #pragma unroll
    for (int off = 16; off > 0; off >>= 1)
        m = fmaxf(m, __shfl_xor_sync(0xFFFFFFFFu, m, off));

    // Block max broadcast
    __shared__ float s_w[8];
    __shared__ int   s_i[8];
    if (lane == 0) s_w[wid] = m;
    __syncthreads();
    float bm = s_w[0];
    #pragma unroll
    for (int w = 1; w < 8; w++) bm = fmaxf(bm, s_w[w]);

    // Index recovery: smallest global index whose value equals bm.
    int cand = 0x7FFFFFFF;
    if (wide) {
        int g0 = tid * 4, g1 = (tid + 256) * 4, g2 = (tid + 512) * 4, g3 = (tid + 768) * 4;
        if (a.x == bm) cand = min(cand, g0    );
        if (a.y == bm) cand = min(cand, g0 + 1);
        if (a.z == bm) cand = min(cand, g0 + 2);
        if (a.w == bm) cand = min(cand, g0 + 3);
        if (b.x == bm) cand = min(cand, g1    );
        if (b.y == bm) cand = min(cand, g1 + 1);
        if (b.z == bm) cand = min(cand, g1 + 2);
        if (b.w == bm) cand = min(cand, g1 + 3);
        if (c.x == bm) cand = min(cand, g2    );
        if (c.y == bm) cand = min(cand, g2 + 1);
        if (c.z == bm) cand = min(cand, g2 + 2);
        if (c.w == bm) cand = min(cand, g2 + 3);
        if (d.x == bm) cand = min(cand, g3    );
        if (d.y == bm) cand = min(cand, g3 + 1);
        if (d.z == bm) cand = min(cand, g3 + 2);
        if (d.w == bm) cand = min(cand, g3 + 3);
    } else {
        int g0 = tid * 4;
        if (a.x == bm) cand = min(cand, g0    );
        if (a.y == bm) cand = min(cand, g0 + 1);
        if (a.z == bm) cand = min(cand, g0 + 2);
        if (a.w == bm) cand = min(cand, g0 + 3);
    }

    // Warp min over candidates
    #pragma unroll
    for (int off = 16; off > 0; off >>= 1)
        cand = min(cand, __shfl_xor_sync(0xFFFFFFFFu, cand, off));
    if (lane == 0) s_i[wid] = cand;
    __syncthreads();
    if (tid == 0) {
        int i = s_i[0];
        #pragma unroll
        for (int w = 1; w < 8; w++) i = min(i, s_i[w]);
        dest[row] = i;
    }
}

// ---------------------------------------------------------------------------
// Compose route once: route[s] = dest3[dest2[dest1[s]]]. Tables are L2-hot.
// ---------------------------------------------------------------------------
__global__ void __launch_bounds__(256) compose_kernel()
{
    int s = blockIdx.x * 256 + threadIdx.x;
    g_route[s] = g_dest3[g_dest2[g_dest1[s]]];
}

// ---------------------------------------------------------------------------
// Scatter: one block (1024 threads) per batch. One int4 of x and route per
// thread, 4 shared-memory atomics, then a single coalesced float store.
// 4KB smem -> high occupancy; 32+ warps/SM hide atomic/load latency.
// ---------------------------------------------------------------------------
__global__ void __launch_bounds__(1024) scatter_kernel(
    const int* __restrict__ x, float* __restrict__ out)
{
    __shared__ int acc[N_OUT];
    const int b   = blockIdx.x;
    const int tid = threadIdx.x;

    if (tid < N_OUT) acc[tid] = 0;
    __syncthreads();

    const int4* __restrict__ xb4 =
        reinterpret_cast<const int4*>(x + (size_t)b * N_IN);
    const int4* __restrict__ r4 = reinterpret_cast<const int4*>(g_route);

    int4 v = xb4[tid];               // DRAM stream, coalesced
    int4 r = r4[tid];                // L2-hot, coalesced
    atomicAdd(&acc[r.x], v.x);
    atomicAdd(&acc[r.y], v.y);
    atomicAdd(&acc[r.z], v.z);
    atomicAdd(&acc[r.w], v.w);
    __syncthreads();

    if (tid < N_OUT)
        out[(size_t)b * N_OUT + tid] = (float)acc[tid];
}

// ---------------------------------------------------------------------------
extern "C" void kernel_launch(void* const* d_in, const int* in_sizes, int n_in,
                              void* d_out, int out_size)
{
    const int*   x  = (const int*)d_in[0];
    const float* W1 = (const float*)d_in[1];
    const float* W2 = (const float*)d_in[2];
    const float* W3 = (const float*)d_in[3];
    float* out = (float*)d_out;

    argmax_all_kernel<<<3 * N_IN, 256>>>(W1, W2, W3);
    compose_kernel<<<N_IN / 256, 256>>>();
    scatter_kernel<<<B, 1024>>>(x, out);
}